// round 7
// baseline (speedup 1.0000x reference)
#include <cuda_runtime.h>
#include <math.h>

// GraphQNN: h = tanh(W @ x); exp_val computed analytically (Heisenberg picture).
//
//   layer-1 CNOT chain: Z_0 invariant; layer-1 RX(t') on q0: Z -> cos t' Z + sin t' Y
//   layer-0 CNOT chain: Z_0 -> Z_0 ; Y_0 -> Y_0 X_1
//   product state per qubit q: RZ(p_q) RX(t_q) RY(2 h_q)|0>
//     <Z>_0 = cos t0 cos 2h0
//     <Y>_0 = sin p0 sin 2h0 - cos p0 sin t0 cos 2h0
//     <X>_1 = cos p1 sin 2h1 + sin p1 sin t1 cos 2h1
//   exp_val = cos t' <Z>_0 + sin t' <Y>_0 <X>_1     (t' = q_params[46])
//
// R7: barrier-free multi-SM. 6 blocks x 4 warps, one warp per h-row
// (row = 4*blockIdx + warp), zero smem/barriers; block 5 warp 3 is the
// self-contained tail warp (redundant rows 0&1 dots + fast-trig scalar).
// Cuts per-SM L1tex wavefront load ~6x vs the single-block R6.

#define NQ 23
#define IN_DIM 1024

__global__ void __launch_bounds__(128)
graphqnn_kernel(const float* __restrict__ x,
                const float* __restrict__ W,
                const float* __restrict__ qp,
                float* __restrict__ out) {
    const int warp = threadIdx.x >> 5;
    const int lane = threadIdx.x & 31;
    const int row  = blockIdx.x * 4 + warp;   // 0..23; row 23 = tail role

    const float4* xr = reinterpret_cast<const float4*>(x);

    if (row < NQ) {
        // ---- h-row warp: 1024-dot, 8 float4 per lane, 4 accumulators ----
        const float4* wr = reinterpret_cast<const float4*>(W + row * IN_DIM);
        float4 a[8], b[8];
        #pragma unroll
        for (int i = 0; i < 8; ++i) { a[i] = wr[lane + 32 * i]; b[i] = xr[lane + 32 * i]; }

        float s0 = 0.f, s1 = 0.f, s2 = 0.f, s3 = 0.f;
        #pragma unroll
        for (int i = 0; i < 8; i += 4) {
            s0 += a[i+0].x*b[i+0].x + a[i+0].y*b[i+0].y + a[i+0].z*b[i+0].z + a[i+0].w*b[i+0].w;
            s1 += a[i+1].x*b[i+1].x + a[i+1].y*b[i+1].y + a[i+1].z*b[i+1].z + a[i+1].w*b[i+1].w;
            s2 += a[i+2].x*b[i+2].x + a[i+2].y*b[i+2].y + a[i+2].z*b[i+2].z + a[i+2].w*b[i+2].w;
            s3 += a[i+3].x*b[i+3].x + a[i+3].y*b[i+3].y + a[i+3].z*b[i+3].z + a[i+3].w*b[i+3].w;
        }
        float s = (s0 + s1) + (s2 + s3);
        #pragma unroll
        for (int o = 16; o > 0; o >>= 1)
            s += __shfl_xor_sync(0xffffffffu, s, o);
        if (lane == 0) out[row] = tanhf(s);
    } else if (row == NQ) {
        // ---- tail warp: lanes 0-15 -> row 0 dot, lanes 16-31 -> row 1 dot ----
        const int half = lane >> 4;          // 0 or 1 = row
        const int hl   = lane & 15;          // lane within half
        const float4* wr = reinterpret_cast<const float4*>(W + half * IN_DIM);

        float s0 = 0.f, s1 = 0.f, s2 = 0.f, s3 = 0.f;
        #pragma unroll
        for (int i = 0; i < 16; i += 4) {
            float4 a0 = wr[hl + 16*(i+0)], b0 = xr[hl + 16*(i+0)];
            float4 a1 = wr[hl + 16*(i+1)], b1 = xr[hl + 16*(i+1)];
            float4 a2 = wr[hl + 16*(i+2)], b2 = xr[hl + 16*(i+2)];
            float4 a3 = wr[hl + 16*(i+3)], b3 = xr[hl + 16*(i+3)];
            s0 += a0.x*b0.x + a0.y*b0.y + a0.z*b0.z + a0.w*b0.w;
            s1 += a1.x*b1.x + a1.y*b1.y + a1.z*b1.z + a1.w*b1.w;
            s2 += a2.x*b2.x + a2.y*b2.y + a2.z*b2.z + a2.w*b2.w;
            s3 += a3.x*b3.x + a3.y*b3.y + a3.z*b3.z + a3.w*b3.w;
        }
        float s = (s0 + s1) + (s2 + s3);
        // reduce within each 16-lane half
        #pragma unroll
        for (int o = 8; o > 0; o >>= 1)
            s += __shfl_xor_sync(0xffffffffu, s, o);

        float h  = tanhf(s);                              // lane0: h0, lane16: h1
        float ho = __shfl_sync(0xffffffffu, h, 16);       // h1 (valid in lane 0)

        if (lane == 0) {
            float h0 = h, h1 = ho;
            float ct0, st0, cp0, sp0, st1, cp1, sp1, ctp, stp;
            __sincosf(qp[0], &st0, &ct0);       // t0
            __sincosf(qp[1], &sp0, &cp0);       // p0
            st1 = __sinf(qp[2]);                // t1
            __sincosf(qp[3], &sp1, &cp1);       // p1
            __sincosf(qp[2 * NQ], &stp, &ctp);  // t' = q_params[46]

            float c2h0, s2h0, c2h1, s2h1;
            __sincosf(2.0f * h0, &s2h0, &c2h0);
            __sincosf(2.0f * h1, &s2h1, &c2h1);

            float z0 = ct0 * c2h0;
            float y0 = sp0 * s2h0 - cp0 * st0 * c2h0;
            float x1 = cp1 * s2h1 + sp1 * st1 * c2h1;
            out[NQ] = ctp * z0 + stp * y0 * x1;
        }
    }
}

extern "C" void kernel_launch(void* const* d_in, const int* in_sizes, int n_in,
                              void* d_out, int out_size) {
    const float* x  = (const float*)d_in[0];
    const float* W  = (const float*)d_in[1];
    const float* qp = (const float*)d_in[2];
    float* out = (float*)d_out;
    graphqnn_kernel<<<6, 128>>>(x, W, qp, out);
}

// round 8
// speedup vs baseline: 1.0435x; 1.0435x over previous
#include <cuda_runtime.h>
#include <math.h>

// GraphQNN: h = tanh(W @ x); exp_val computed analytically (Heisenberg picture).
//
//   layer-1 CNOT chain: Z_0 invariant; layer-1 RX(t') on q0: Z -> cos t' Z + sin t' Y
//   layer-0 CNOT chain: Z_0 -> Z_0 ; Y_0 -> Y_0 X_1
//   product state per qubit q: RZ(p_q) RX(t_q) RY(2 h_q)|0>
//     <Z>_0 = cos t0 cos 2h0
//     <Y>_0 = sin p0 sin 2h0 - cos p0 sin t0 cos 2h0
//     <X>_1 = cos p1 sin 2h1 + sin p1 sin t1 cos 2h1
//   exp_val = cos t' <Z>_0 + sin t' <Y>_0 <X>_1     (t' = q_params[46])
//
// R8: 2 blocks x 12 warps, barrier-free, zero smem. Halves the per-SM L1tex
// wavefront load vs single-block R6 while keeping 3 warps/SMSP for latency
// hiding (R7's 1 warp/SMSP starved issue). Block 0: rows 0-11; block 1:
// rows 12-22 + self-contained tail warp (redundant rows 0&1 + fast trig).

#define NQ 23
#define IN_DIM 1024

__global__ void __launch_bounds__(384)
graphqnn_kernel(const float* __restrict__ x,
                const float* __restrict__ W,
                const float* __restrict__ qp,
                float* __restrict__ out) {
    const int warp = threadIdx.x >> 5;
    const int lane = threadIdx.x & 31;
    const int slot = blockIdx.x * 12 + warp;   // 0..23; slot 23 = tail role

    const float4* xr = reinterpret_cast<const float4*>(x);

    if (slot < NQ) {
        // ---- h-row warp: 1024-dot, 8 float4 per lane, 4 accumulators ----
        const float4* wr = reinterpret_cast<const float4*>(W + slot * IN_DIM);
        float4 a[8], b[8];
        #pragma unroll
        for (int i = 0; i < 8; ++i) { a[i] = wr[lane + 32 * i]; b[i] = xr[lane + 32 * i]; }

        float s0 = 0.f, s1 = 0.f, s2 = 0.f, s3 = 0.f;
        #pragma unroll
        for (int i = 0; i < 8; i += 4) {
            s0 += a[i+0].x*b[i+0].x + a[i+0].y*b[i+0].y + a[i+0].z*b[i+0].z + a[i+0].w*b[i+0].w;
            s1 += a[i+1].x*b[i+1].x + a[i+1].y*b[i+1].y + a[i+1].z*b[i+1].z + a[i+1].w*b[i+1].w;
            s2 += a[i+2].x*b[i+2].x + a[i+2].y*b[i+2].y + a[i+2].z*b[i+2].z + a[i+2].w*b[i+2].w;
            s3 += a[i+3].x*b[i+3].x + a[i+3].y*b[i+3].y + a[i+3].z*b[i+3].z + a[i+3].w*b[i+3].w;
        }
        float s = (s0 + s1) + (s2 + s3);
        #pragma unroll
        for (int o = 16; o > 0; o >>= 1)
            s += __shfl_xor_sync(0xffffffffu, s, o);
        if (lane == 0) out[slot] = tanhf(s);
    } else if (slot == NQ) {
        // ---- tail warp: lanes 0-15 -> row 0 dot, lanes 16-31 -> row 1 dot ----
        const int half = lane >> 4;          // 0 or 1 = row
        const int hl   = lane & 15;          // lane within half
        const float4* wr = reinterpret_cast<const float4*>(W + half * IN_DIM);

        float s0 = 0.f, s1 = 0.f, s2 = 0.f, s3 = 0.f;
        #pragma unroll
        for (int i = 0; i < 16; i += 4) {
            float4 a0 = wr[hl + 16*(i+0)], b0 = xr[hl + 16*(i+0)];
            float4 a1 = wr[hl + 16*(i+1)], b1 = xr[hl + 16*(i+1)];
            float4 a2 = wr[hl + 16*(i+2)], b2 = xr[hl + 16*(i+2)];
            float4 a3 = wr[hl + 16*(i+3)], b3 = xr[hl + 16*(i+3)];
            s0 += a0.x*b0.x + a0.y*b0.y + a0.z*b0.z + a0.w*b0.w;
            s1 += a1.x*b1.x + a1.y*b1.y + a1.z*b1.z + a1.w*b1.w;
            s2 += a2.x*b2.x + a2.y*b2.y + a2.z*b2.z + a2.w*b2.w;
            s3 += a3.x*b3.x + a3.y*b3.y + a3.z*b3.z + a3.w*b3.w;
        }
        float s = (s0 + s1) + (s2 + s3);
        // reduce within each 16-lane half
        #pragma unroll
        for (int o = 8; o > 0; o >>= 1)
            s += __shfl_xor_sync(0xffffffffu, s, o);

        float h  = tanhf(s);                              // lane0: h0, lane16: h1
        float ho = __shfl_sync(0xffffffffu, h, 16);       // h1 (valid in lane 0)

        if (lane == 0) {
            float h0 = h, h1 = ho;
            float ct0, st0, cp0, sp0, st1, cp1, sp1, ctp, stp;
            __sincosf(qp[0], &st0, &ct0);       // t0
            __sincosf(qp[1], &sp0, &cp0);       // p0
            st1 = __sinf(qp[2]);                // t1
            __sincosf(qp[3], &sp1, &cp1);       // p1
            __sincosf(qp[2 * NQ], &stp, &ctp);  // t' = q_params[46]

            float c2h0, s2h0, c2h1, s2h1;
            __sincosf(2.0f * h0, &s2h0, &c2h0);
            __sincosf(2.0f * h1, &s2h1, &c2h1);

            float z0 = ct0 * c2h0;
            float y0 = sp0 * s2h0 - cp0 * st0 * c2h0;
            float x1 = cp1 * s2h1 + sp1 * st1 * c2h1;
            out[NQ] = ctp * z0 + stp * y0 * x1;
        }
    }
}

extern "C" void kernel_launch(void* const* d_in, const int* in_sizes, int n_in,
                              void* d_out, int out_size) {
    const float* x  = (const float*)d_in[0];
    const float* W  = (const float*)d_in[1];
    const float* qp = (const float*)d_in[2];
    float* out = (float*)d_out;
    graphqnn_kernel<<<2, 384>>>(x, W, qp, out);
}